// round 4
// baseline (speedup 1.0000x reference)
#include <cuda_runtime.h>
#include <math.h>
#include <stdint.h>

// Problem constants (fixed shapes)
#define BATCH   4
#define NQ      5440
#define NV      5440
#define EMBED   256
#define NHEADS  8
#define NLEV    4
#define NPTS    4
#define HDIM    32
#define MTOT    (BATCH * NQ)          // 21760 = 170 * 128

// ---------------------------------------------------------------------------
// Scratch (static device globals — no allocation anywhere)
// ---------------------------------------------------------------------------
__device__ float g_v[MTOT * EMBED];                    // projected value (B,Nv,8,32)
__device__ float g_off[MTOT * EMBED];                  // sampling offsets (B,Nq,8,4,4,2)
__device__ float g_aw[MTOT * (NHEADS * NLEV * NPTS)];  // attn logits (B,Nq,8,16)
__device__ float g_samp[MTOT * EMBED];                 // pre-out-proj (B,Nq,8,32)

// ---------------------------------------------------------------------------
// SGEMM: C[M,N] = A[M,K] @ W[K,N] + bias[N]
// 128x128 block tile, BK=16, 256 threads, 8x8 register tile per thread.
// Requires M%128==0, N%128==0, K%16==0 (true for all our shapes).
// ---------------------------------------------------------------------------
#define GBM 128
#define GBN 128
#define GBK 16
#define GTM 8
#define GTN 8

__global__ __launch_bounds__(256)
void sgemm_bias(const float* __restrict__ A, const float* __restrict__ W,
                const float* __restrict__ bias, float* __restrict__ C,
                int M, int N, int K)
{
    __shared__ float As[GBK][GBM + 4];   // +4 pad: kills 4-way store conflicts
    __shared__ float Bs[GBK][GBN];

    const int tid = threadIdx.x;
    const int bm = blockIdx.y * GBM;
    const int bn = blockIdx.x * GBN;
    const int tr = (tid >> 4) * GTM;     // 0..120
    const int tc = (tid & 15) * GTN;     // 0..120

    float acc[GTM][GTN];
#pragma unroll
    for (int i = 0; i < GTM; i++)
#pragma unroll
        for (int j = 0; j < GTN; j++) acc[i][j] = 0.0f;

    for (int k0 = 0; k0 < K; k0 += GBK) {
        // Load A tile: 128 rows x 16 k = 512 float4, 2 per thread (coalesced).
#pragma unroll
        for (int t = 0; t < 2; t++) {
            int idx = tid + t * 256;
            int row = idx >> 2;              // 0..127
            int kc  = (idx & 3) * 4;         // 0,4,8,12
            float4 a = *(const float4*)&A[(size_t)(bm + row) * K + k0 + kc];
            As[kc + 0][row] = a.x;
            As[kc + 1][row] = a.y;
            As[kc + 2][row] = a.z;
            As[kc + 3][row] = a.w;
        }
        // Load B tile: 16 k x 128 n = 512 float4, 2 per thread (coalesced).
#pragma unroll
        for (int t = 0; t < 2; t++) {
            int idx = tid + t * 256;
            int kr = idx >> 5;               // 0..15
            int nc = (idx & 31) * 4;         // 0..124
            float4 b = *(const float4*)&W[(size_t)(k0 + kr) * N + bn + nc];
            *(float4*)&Bs[kr][nc] = b;
        }
        __syncthreads();

#pragma unroll
        for (int kk = 0; kk < GBK; kk++) {
            float a[GTM], b[GTN];
            *(float4*)&a[0] = *(const float4*)&As[kk][tr];
            *(float4*)&a[4] = *(const float4*)&As[kk][tr + 4];
            *(float4*)&b[0] = *(const float4*)&Bs[kk][tc];
            *(float4*)&b[4] = *(const float4*)&Bs[kk][tc + 4];
#pragma unroll
            for (int i = 0; i < GTM; i++)
#pragma unroll
                for (int j = 0; j < GTN; j++)
                    acc[i][j] = fmaf(a[i], b[j], acc[i][j]);
        }
        __syncthreads();
    }

    float bv[GTN];
#pragma unroll
    for (int j = 0; j < GTN; j++) bv[j] = bias[bn + tc + j];

#pragma unroll
    for (int i = 0; i < GTM; i++) {
        float4 r0, r1;
        r0.x = acc[i][0] + bv[0]; r0.y = acc[i][1] + bv[1];
        r0.z = acc[i][2] + bv[2]; r0.w = acc[i][3] + bv[3];
        r1.x = acc[i][4] + bv[4]; r1.y = acc[i][5] + bv[5];
        r1.z = acc[i][6] + bv[6]; r1.w = acc[i][7] + bv[7];
        float* cp = &C[(size_t)(bm + tr + i) * N + bn + tc];
        *(float4*)&cp[0] = r0;
        *(float4*)&cp[4] = r1;
    }
}

// ---------------------------------------------------------------------------
// Deformable sampling + softmax.
// One warp per (b, q, head). Lane = head dim (0..31).
// Lanes 0..15 each own one (level, point): softmax weight + bilinear setup.
// Gather loop broadcasts (row, weight) and all 32 lanes do coalesced 128B reads.
// ---------------------------------------------------------------------------
__global__ __launch_bounds__(256)
void msda_sample(const float* __restrict__ vbuf, const float* __restrict__ offbuf,
                 const float* __restrict__ awbuf, const float* __restrict__ refp,
                 float* __restrict__ samp)
{
    const unsigned FULL = 0xffffffffu;
    int wg = (blockIdx.x * blockDim.x + threadIdx.x) >> 5;  // global warp id
    int lane = threadIdx.x & 31;
    if (wg >= MTOT * NHEADS) return;

    int h  = wg & 7;
    int bq = wg >> 3;          // b*NQ + q
    int b  = bq / NQ;

    // ---- softmax over 16 (level,point) logits ----
    float logit = -1e30f;
    if (lane < 16)
        logit = awbuf[(size_t)bq * (NHEADS * NLEV * NPTS) + h * 16 + lane];
    float m = logit;
#pragma unroll
    for (int o = 16; o >= 1; o >>= 1) m = fmaxf(m, __shfl_xor_sync(FULL, m, o));
    float e = (lane < 16) ? __expf(logit - m) : 0.0f;
    float s = e;
#pragma unroll
    for (int o = 16; o >= 1; o >>= 1) s += __shfl_xor_sync(FULL, s, o);
    float wgt = e / s;

    // ---- per-point bilinear setup (lanes 0..15) ----
    int   idx[4];
    float cw[4];
#pragma unroll
    for (int c = 0; c < 4; c++) { idx[c] = 0; cw[c] = 0.0f; }

    if (lane < 16) {
        int l = lane >> 2;                         // level
        int W = 64 >> l, H = 64 >> l;
        int base = (16384 - (16384 >> (2 * l))) / 3;   // {0,4096,5120,5376}
        float Wf = (float)W, Hf = (float)H;

        const float* rp = refp + ((size_t)bq * NLEV + l) * 2;
        const float* op = offbuf + (size_t)bq * EMBED + h * 32 + 2 * lane;

        float locx = rp[0] + op[0] * (1.0f / Wf);
        float locy = rp[1] + op[1] * (1.0f / Hf);
        float px = locx * Wf - 0.5f;     // align_corners=False pixel coords
        float py = locy * Hf - 0.5f;
        float x0f = floorf(px), y0f = floorf(py);
        float wx = px - x0f, wy = py - y0f;
        int x0 = (int)x0f, y0 = (int)y0f;

#pragma unroll
        for (int c = 0; c < 4; c++) {
            int dx = c & 1, dy = c >> 1;
            int xi = x0 + dx, yi = y0 + dy;
            bool valid = (xi >= 0) & (xi < W) & (yi >= 0) & (yi < H);
            int xc = min(max(xi, 0), W - 1);
            int yc = min(max(yi, 0), H - 1);
            idx[c] = base + yc * W + xc;
            float wc = (dx ? wx : 1.0f - wx) * (dy ? wy : 1.0f - wy);
            cw[c] = valid ? wgt * wc : 0.0f;
        }
    }

    // ---- gather: 16 points x 4 corners, 128B coalesced rows of v ----
    const float* vb = vbuf + (size_t)b * NV * EMBED + h * HDIM + lane;
    float acc = 0.0f;
#pragma unroll
    for (int i = 0; i < 16; i++) {
#pragma unroll
        for (int c = 0; c < 4; c++) {
            int   r = __shfl_sync(FULL, idx[c], i);
            float w = __shfl_sync(FULL, cw[c], i);
            acc = fmaf(w, __ldg(vb + (size_t)r * EMBED), acc);
        }
    }

    samp[(size_t)bq * EMBED + h * HDIM + lane] = acc;
}

// ---------------------------------------------------------------------------
// kernel_launch
// ---------------------------------------------------------------------------
extern "C" void kernel_launch(void* const* d_in, const int* in_sizes, int n_in,
                              void* d_out, int out_size)
{
    const float* query   = (const float*)d_in[0];
    const float* value   = (const float*)d_in[1];
    const float* refp    = (const float*)d_in[2];
    const float* vproj_w = (const float*)d_in[3];
    const float* vproj_b = (const float*)d_in[4];
    const float* off_w   = (const float*)d_in[5];
    const float* off_b   = (const float*)d_in[6];
    const float* aw_w    = (const float*)d_in[7];
    const float* aw_b    = (const float*)d_in[8];
    const float* out_w   = (const float*)d_in[9];
    const float* out_b   = (const float*)d_in[10];
    float* out = (float*)d_out;

    float *v, *off, *aw, *samp;
    cudaGetSymbolAddress((void**)&v,    g_v);
    cudaGetSymbolAddress((void**)&off,  g_off);
    cudaGetSymbolAddress((void**)&aw,   g_aw);
    cudaGetSymbolAddress((void**)&samp, g_samp);

    dim3 blk(256);
    // value / offsets / attn projections (independent, sequential is fine)
    sgemm_bias<<<dim3(2, MTOT / GBM), blk>>>(value, vproj_w, vproj_b, v,    MTOT, 256, 256);
    sgemm_bias<<<dim3(2, MTOT / GBM), blk>>>(query, off_w,   off_b,   off,  MTOT, 256, 256);
    sgemm_bias<<<dim3(1, MTOT / GBM), blk>>>(query, aw_w,    aw_b,    aw,   MTOT, 128, 256);

    // softmax + deformable bilinear sampling: 174080 warps, 8 per block
    msda_sample<<<(MTOT * NHEADS) / 8, blk>>>(v, off, aw, refp, samp);

    // output projection straight into d_out
    sgemm_bias<<<dim3(2, MTOT / GBM), blk>>>(samp, out_w, out_b, out, MTOT, 256, 256);
}

// round 9
// speedup vs baseline: 1.6024x; 1.6024x over previous
#include <cuda_runtime.h>
#include <cuda_bf16.h>
#include <math.h>
#include <stdint.h>

// Problem constants (fixed shapes)
#define BATCH   4
#define NQ      5440
#define NV      5440
#define EMBED   256
#define NHEADS  8
#define NLEV    4
#define NPTS    4
#define HDIM    32
#define MTOT    (BATCH * NQ)          // 21760 = 170 * 128

// ---------------------------------------------------------------------------
// Scratch (static device globals — no allocation anywhere)
// ---------------------------------------------------------------------------
__device__ float g_v[MTOT * EMBED];                    // projected value (f32)
__device__ float g_off[MTOT * EMBED];                  // sampling offsets
__device__ float g_aw[MTOT * 128];                     // attn logits

__device__ __nv_bfloat16 g_qhi[MTOT * EMBED],  g_qlo[MTOT * EMBED];   // query split
__device__ __nv_bfloat16 g_vhi[MTOT * EMBED],  g_vlo[MTOT * EMBED];   // value split
__device__ __nv_bfloat16 g_shi[MTOT * EMBED],  g_slo[MTOT * EMBED];   // sampled split

// transposed weight splits [N][K=256]
__device__ __nv_bfloat16 g_wvh[256 * 256], g_wvl[256 * 256];   // value_proj
__device__ __nv_bfloat16 g_wfh[256 * 256], g_wfl[256 * 256];   // offsets
__device__ __nv_bfloat16 g_wah[128 * 256], g_wal[128 * 256];   // attn
__device__ __nv_bfloat16 g_wuh[256 * 256], g_wul[256 * 256];   // out_proj

// ---------------------------------------------------------------------------
// Helpers
// ---------------------------------------------------------------------------
__device__ __forceinline__ uint32_t smem_u32(const void* p) {
    uint32_t a;
    asm("{ .reg .u64 t; cvta.to.shared.u64 t, %1; cvt.u32.u64 %0, t; }" : "=r"(a) : "l"(p));
    return a;
}

#define CP_ASYNC16(dst, src) \
    asm volatile("cp.async.cg.shared.global [%0], [%1], 16;" :: "r"(dst), "l"(src) : "memory")
#define CP_COMMIT() asm volatile("cp.async.commit_group;" ::: "memory")
#define CP_WAIT(n)  asm volatile("cp.async.wait_group %0;" :: "n"(n) : "memory")

__device__ __forceinline__ void ldm4(uint32_t* r, uint32_t addr) {
    asm volatile("ldmatrix.sync.aligned.m8n8.x4.shared.b16 {%0,%1,%2,%3}, [%4];"
                 : "=r"(r[0]), "=r"(r[1]), "=r"(r[2]), "=r"(r[3]) : "r"(addr));
}
__device__ __forceinline__ void mma16816(float* d, const uint32_t* a, const uint32_t* b) {
    asm volatile(
        "mma.sync.aligned.m16n8k16.row.col.f32.bf16.bf16.f32 "
        "{%0,%1,%2,%3}, {%4,%5,%6,%7}, {%8,%9}, {%0,%1,%2,%3};"
        : "+f"(d[0]), "+f"(d[1]), "+f"(d[2]), "+f"(d[3])
        : "r"(a[0]), "r"(a[1]), "r"(a[2]), "r"(a[3]), "r"(b[0]), "r"(b[1]));
}

// ---------------------------------------------------------------------------
// Split decompose kernels: f32 -> bf16 hi + bf16 lo(residual)
// ---------------------------------------------------------------------------
__global__ __launch_bounds__(256)
void decomp_act(const float4* __restrict__ src, uint2* __restrict__ hi,
                uint2* __restrict__ lo, int n4) {
    int i = blockIdx.x * 256 + threadIdx.x;
    if (i >= n4) return;
    float4 x = src[i];
    float v[4] = {x.x, x.y, x.z, x.w};
    union { __nv_bfloat16 b[4]; uint2 u; } H, L;
#pragma unroll
    for (int j = 0; j < 4; j++) {
        H.b[j] = __float2bfloat16(v[j]);
        L.b[j] = __float2bfloat16(v[j] - __bfloat162float(H.b[j]));
    }
    hi[i] = H.u;
    lo[i] = L.u;
}

__global__ __launch_bounds__(256)
void decomp_wT(const float* __restrict__ W, __nv_bfloat16* __restrict__ hiT,
               __nv_bfloat16* __restrict__ loT, int Nw) {
    int i = blockIdx.x * 256 + threadIdx.x;
    if (i >= 256 * Nw) return;
    int k = i / Nw, n = i % Nw;
    float x = W[i];
    __nv_bfloat16 h = __float2bfloat16(x);
    hiT[n * 256 + k] = h;
    loT[n * 256 + k] = __float2bfloat16(x - __bfloat162float(h));
}

// ---------------------------------------------------------------------------
// Tensor-core GEMM (legacy mma.sync path; works under compute_103):
//   C[M,N] = A[M,256] @ W[256,N] + bias, bf16 3-product split, fp32 accum.
// Block 128x128, BK=32, 8 warps (4M x 2N), warp tile 32x64.
// 2-stage cp.async pipeline. SMEM tiles: [row][32 bf16] with 16B-seg XOR
// swizzle (seg ^ (row&3)) — conflict-free stores, <=2-way on ldmatrix.
// ---------------------------------------------------------------------------
#define STAGE_BYTES 32768            // 4 tiles x 8KB (Ahi,Alo,Bhi,Blo)
#define GEMM_SMEM   (2 * STAGE_BYTES)

__device__ void mma_gemm_body(char* sm,
                              const __nv_bfloat16* __restrict__ Ahi,
                              const __nv_bfloat16* __restrict__ Alo,
                              const __nv_bfloat16* __restrict__ Bhi,
                              const __nv_bfloat16* __restrict__ Blo,
                              const float* __restrict__ bias,
                              float* __restrict__ C, int N, int bm, int bn)
{
    const int t = threadIdx.x, lane = t & 31, warp = t >> 5;
    const int wm = (warp >> 1) * 32;          // warp M offset in tile
    const int wn = (warp & 1) * 64;           // warp N offset in tile

    const uint32_t sbase = smem_u32(sm);

    // ---- cp.async source bases (per-thread constants) ----
    const char* gsrc[4] = {
        (const char*)(Ahi + (size_t)bm * 256), (const char*)(Alo + (size_t)bm * 256),
        (const char*)(Bhi + (size_t)bn * 256), (const char*)(Blo + (size_t)bn * 256)
    };
    const int lrow = t >> 2, lseg = t & 3;    // loader: 64 rows x 4 segs per iter

    float acc[2][8][4];
#pragma unroll
    for (int a = 0; a < 2; a++)
#pragma unroll
        for (int b = 0; b < 8; b++)
#pragma unroll
            for (int d = 0; d < 4; d++) acc[a][b][d] = 0.0f;

    // ---- ldmatrix address components (constant per thread) ----
    // A: row = wm + mt*16 + (lane&15), seg = kk*2 + (lane>>4)
    const int arow_l = lane & 15;
    const int aseg_l = lane >> 4;
    // B: row = wn + np*16 + (lane&7) + ((lane>=16)?8:0), seg = kk*2 + ((lane>>3)&1)
    const int brow_l = (lane & 7) + ((lane >> 4) << 3);
    const int bseg_l = (lane >> 3) & 1;

#define LOAD_CHUNK(c, s) do {                                                   \
        uint32_t st_ = sbase + (s) * STAGE_BYTES;                               \
        _Pragma("unroll")                                                       \
        for (int it_ = 0; it_ < 2; it_++) {                                     \
            int row_ = lrow + it_ * 64;                                         \
            uint32_t so_ = (uint32_t)(row_ * 64 + ((lseg ^ (row_ & 3)) << 4));  \
            size_t go_ = (size_t)row_ * 512 + (size_t)(c) * 64 + lseg * 16;     \
            CP_ASYNC16(st_ +      0 + so_, gsrc[0] + go_);                      \
            CP_ASYNC16(st_ +  8192 + so_, gsrc[1] + go_);                       \
            CP_ASYNC16(st_ + 16384 + so_, gsrc[2] + go_);                       \
            CP_ASYNC16(st_ + 24576 + so_, gsrc[3] + go_);                       \
        }                                                                       \
        CP_COMMIT();                                                            \
    } while (0)

    LOAD_CHUNK(0, 0);

    for (int c = 0; c < 8; c++) {
        if (c < 7) { LOAD_CHUNK(c + 1, (c + 1) & 1); CP_WAIT(1); }
        else       { CP_WAIT(0); }
        __syncthreads();

        const uint32_t st = sbase + (c & 1) * STAGE_BYTES;
#pragma unroll
        for (int kk = 0; kk < 2; kk++) {
            // A fragments (hi & lo) for both 16-row m-tiles
            uint32_t ah[2][4], al[2][4];
#pragma unroll
            for (int mt = 0; mt < 2; mt++) {
                int row = wm + mt * 16 + arow_l;
                int seg = kk * 2 + aseg_l;
                uint32_t ad = st + (uint32_t)(row * 64 + ((seg ^ (row & 3)) << 4));
                ldm4(ah[mt], ad);
                ldm4(al[mt], ad + 8192);
            }
            // B fragments: 4 ldmatrix.x4 cover 8 n-tiles (2 per ldm), hi & lo
#pragma unroll
            for (int np = 0; np < 4; np++) {
                int row = wn + np * 16 + brow_l;
                int seg = kk * 2 + bseg_l;
                uint32_t bd = st + 16384 + (uint32_t)(row * 64 + ((seg ^ (row & 3)) << 4));
                uint32_t bh[4], bl[4];
                ldm4(bh, bd);
                ldm4(bl, bd + 8192);
#pragma unroll
                for (int half = 0; half < 2; half++) {
                    int nt = np * 2 + half;
#pragma unroll
                    for (int mt = 0; mt < 2; mt++) {
                        mma16816(acc[mt][nt], ah[mt], bh + half * 2);  // hi*hi
                        mma16816(acc[mt][nt], ah[mt], bl + half * 2);  // hi*lo
                        mma16816(acc[mt][nt], al[mt], bh + half * 2);  // lo*hi
                    }
                }
            }
        }
        __syncthreads();
    }
#undef LOAD_CHUNK

    // ---- epilogue: d-frag mapping (r = lane>>2, col = 2*(lane&3)) ----
    const int r0 = bm + wm + (lane >> 2);
    const int c0 = bn + wn + (lane & 3) * 2;
#pragma unroll
    for (int nt = 0; nt < 8; nt++) {
        int col = c0 + nt * 8;
        float bx = bias[col - bn - bn ? col : col];  // (no-op guard removed below)
        float b0 = bias[col];
        float b1 = bias[col + 1];
#pragma unroll
        for (int mt = 0; mt < 2; mt++) {
            int row = r0 + mt * 16;
            float2 lo2, hi2;
            lo2.x = acc[mt][nt][0] + b0;
            lo2.y = acc[mt][nt][1] + b1;
            hi2.x = acc[mt][nt][2] + b0;
            hi2.y = acc[mt][nt][3] + b1;
            *(float2*)&C[(size_t)row * N + col]       = lo2;
            *(float2*)&C[(size_t)(row + 8) * N + col] = hi2;
        }
        (void)bx;
    }
}

// Fused launch: value-proj (2 N-tiles) + offsets (2) + attn (1) => grid.x = 5
__global__ __launch_bounds__(256, 1)
void mma_gemm_fused(const __nv_bfloat16* valhi, const __nv_bfloat16* vallo,
                    const __nv_bfloat16* qhi,   const __nv_bfloat16* qlo,
                    const __nv_bfloat16* wvh,   const __nv_bfloat16* wvl,
                    const __nv_bfloat16* wfh,   const __nv_bfloat16* wfl,
                    const __nv_bfloat16* wah,   const __nv_bfloat16* wal,
                    const float* vb, const float* fb, const float* ab,
                    float* Cv, float* Cf, float* Ca) {
    extern __shared__ char smem[];
    int bx = blockIdx.x, bm = blockIdx.y * 128;
    const __nv_bfloat16 *Ah, *Al, *Bh, *Bl;
    const float* bias; float* C; int N, bn;
    if (bx < 2)      { Ah = valhi; Al = vallo; Bh = wvh; Bl = wvl; bias = vb; C = Cv; N = 256; bn = bx * 128; }
    else if (bx < 4) { Ah = qhi;   Al = qlo;   Bh = wfh; Bl = wfl; bias = fb; C = Cf; N = 256; bn = (bx - 2) * 128; }
    else             { Ah = qhi;   Al = qlo;   Bh = wah; Bl = wal; bias = ab; C = Ca; N = 128; bn = 0; }
    mma_gemm_body(smem, Ah, Al, Bh, Bl, bias, C, N, bm, bn);
}

__global__ __launch_bounds__(256, 1)
void mma_gemm_out(const __nv_bfloat16* shi, const __nv_bfloat16* slo,
                  const __nv_bfloat16* wuh, const __nv_bfloat16* wul,
                  const float* ob, float* C) {
    extern __shared__ char smem[];
    mma_gemm_body(smem, shi, slo, wuh, wul, ob, C, 256, blockIdx.y * 128, blockIdx.x * 128);
}

// ---------------------------------------------------------------------------
// Deformable sampling + softmax (one warp per (b,q,head); lane = head dim).
// Setup lanes (<16) precompute BYTE offsets + fused weights; gather loop is
// 2 shfl + LDG + FFMA per corner. Emits bf16 hi/lo split directly.
// ---------------------------------------------------------------------------
__global__ __launch_bounds__(256)
void msda_sample(const float* __restrict__ vbuf, const float* __restrict__ offbuf,
                 const float* __restrict__ awbuf, const float* __restrict__ refp,
                 __nv_bfloat16* __restrict__ shi, __nv_bfloat16* __restrict__ slo)
{
    const unsigned FULL = 0xffffffffu;
    int wg = (blockIdx.x * blockDim.x + threadIdx.x) >> 5;
    int lane = threadIdx.x & 31;
    if (wg >= MTOT * NHEADS) return;

    int h  = wg & 7;
    int bq = wg >> 3;
    int b  = bq / NQ;

    // softmax over 16 (level,point) logits
    float logit = -1e30f;
    if (lane < 16) logit = awbuf[(size_t)bq * 128 + h * 16 + lane];
    float m = logit;
#pragma unroll
    for (int o = 16; o >= 1; o >>= 1) m = fmaxf(m, __shfl_xor_sync(FULL, m, o));
    float e = (lane < 16) ? __expf(logit - m) : 0.0f;
    float s = e;
#pragma unroll
    for (int o = 16; o >= 1; o >>= 1) s += __shfl_xor_sync(FULL, s, o);
    float wgt = e / s;

    int   boff[4];
    float cw[4];
#pragma unroll
    for (int c = 0; c < 4; c++) { boff[c] = 0; cw[c] = 0.0f; }

    if (lane < 16) {
        int l = lane >> 2;
        int W = 64 >> l, H = 64 >> l;
        int base = (16384 - (16384 >> (2 * l))) / 3;
        float Wf = (float)W, Hf = (float)H;

        const float* rp = refp + ((size_t)bq * NLEV + l) * 2;
        const float* op = offbuf + (size_t)bq * EMBED + h * 32 + 2 * lane;

        float px = (rp[0] + op[0] * (1.0f / Wf)) * Wf - 0.5f;
        float py = (rp[1] + op[1] * (1.0f / Hf)) * Hf - 0.5f;
        float x0f = floorf(px), y0f = floorf(py);
        float wx = px - x0f, wy = py - y0f;
        int x0 = (int)x0f, y0 = (int)y0f;

#pragma unroll
        for (int c = 0; c < 4; c++) {
            int dx = c & 1, dy = c >> 1;
            int xi = x0 + dx, yi = y0 + dy;
            bool valid = (xi >= 0) & (xi < W) & (yi >= 0) & (yi < H);
            int xc = min(max(xi, 0), W - 1);
            int yc = min(max(yi, 0), H - 1);
            boff[c] = (base + yc * W + xc) << 10;          // byte offset (row = 1024B)
            float wc = (dx ? wx : 1.0f - wx) * (dy ? wy : 1.0f - wy);
            cw[c] = valid ? wgt * wc : 0.0f;
        }
    }

    const char* vb = (const char*)vbuf + (size_t)b * NV * 1024 + h * 128 + lane * 4;
    float acc0 = 0.0f, acc1 = 0.0f;
#pragma unroll
    for (int i = 0; i < 16; i++) {
#pragma unroll
        for (int c = 0; c < 4; c += 2) {
            int   o0 = __shfl_sync(FULL, boff[c],     i);
            float w0 = __shfl_sync(FULL, cw[c],       i);
            int   o1 = __shfl_sync(FULL, boff[c + 1], i);
            float w1 = __shfl_sync(FULL, cw[c + 1],   i);
            acc0 = fmaf(w0, *(const float*)(vb + o0), acc0);
            acc1 = fmaf(w1, *(const float*)(vb + o1), acc1);
        }
    }
    float acc = acc0 + acc1;

    size_t o = (size_t)bq * EMBED + h * HDIM + lane;
    __nv_bfloat16 hh = __float2bfloat16(acc);
    shi[o] = hh;
    slo[o] = __float2bfloat16(acc - __bfloat162float(hh));
}

// ---------------------------------------------------------------------------
// kernel_launch
// ---------------------------------------------------------------------------
extern "C" void kernel_launch(void* const* d_in, const int* in_sizes, int n_in,
                              void* d_out, int out_size)
{
    const float* query   = (const float*)d_in[0];
    const float* value   = (const float*)d_in[1];
    const float* refp    = (const float*)d_in[2];
    const float* vproj_w = (const float*)d_in[3];
    const float* vproj_b = (const float*)d_in[4];
    const float* off_w   = (const float*)d_in[5];
    const float* off_b   = (const float*)d_in[6];
    const float* aw_w    = (const float*)d_in[7];
    const float* aw_b    = (const float*)d_in[8];
    const float* out_w   = (const float*)d_in[9];
    const float* out_b   = (const float*)d_in[10];
    float* out = (float*)d_out;

    float *v, *off, *aw;
    __nv_bfloat16 *qhi, *qlo, *vhi, *vlo, *shi, *slo;
    __nv_bfloat16 *wvh, *wvl, *wfh, *wfl, *wah, *wal, *wuh, *wul;
    cudaGetSymbolAddress((void**)&v,   g_v);
    cudaGetSymbolAddress((void**)&off, g_off);
    cudaGetSymbolAddress((void**)&aw,  g_aw);
    cudaGetSymbolAddress((void**)&qhi, g_qhi); cudaGetSymbolAddress((void**)&qlo, g_qlo);
    cudaGetSymbolAddress((void**)&vhi, g_vhi); cudaGetSymbolAddress((void**)&vlo, g_vlo);
    cudaGetSymbolAddress((void**)&shi, g_shi); cudaGetSymbolAddress((void**)&slo, g_slo);
    cudaGetSymbolAddress((void**)&wvh, g_wvh); cudaGetSymbolAddress((void**)&wvl, g_wvl);
    cudaGetSymbolAddress((void**)&wfh, g_wfh); cudaGetSymbolAddress((void**)&wfl, g_wfl);
    cudaGetSymbolAddress((void**)&wah, g_wah); cudaGetSymbolAddress((void**)&wal, g_wal);
    cudaGetSymbolAddress((void**)&wuh, g_wuh); cudaGetSymbolAddress((void**)&wul, g_wul);

    cudaFuncSetAttribute(mma_gemm_fused, cudaFuncAttributeMaxDynamicSharedMemorySize, GEMM_SMEM);
    cudaFuncSetAttribute(mma_gemm_out,   cudaFuncAttributeMaxDynamicSharedMemorySize, GEMM_SMEM);

    const int n4 = MTOT * EMBED / 4;
    decomp_act<<<(n4 + 255) / 256, 256>>>((const float4*)value, (uint2*)vhi, (uint2*)vlo, n4);
    decomp_act<<<(n4 + 255) / 256, 256>>>((const float4*)query, (uint2*)qhi, (uint2*)qlo, n4);
    decomp_wT<<<(256 * 256 + 255) / 256, 256>>>(vproj_w, wvh, wvl, 256);
    decomp_wT<<<(256 * 256 + 255) / 256, 256>>>(off_w,   wfh, wfl, 256);
    decomp_wT<<<(256 * 128 + 255) / 256, 256>>>(aw_w,    wah, wal, 128);
    decomp_wT<<<(256 * 256 + 255) / 256, 256>>>(out_w,   wuh, wul, 256);

    // fused value/offsets/attn projections: 5 N-tiles x 170 M-tiles
    mma_gemm_fused<<<dim3(5, MTOT / 128), 256, GEMM_SMEM>>>(
        vhi, vlo, qhi, qlo, wvh, wvl, wfh, wfl, wah, wal,
        vproj_b, off_b, aw_b, v, off, aw);

    // softmax + deformable bilinear sampling (emits bf16 split directly)
    msda_sample<<<(MTOT * NHEADS) / 8, 256>>>(v, off, aw, refp, shi, slo);

    // output projection straight into d_out
    mma_gemm_out<<<dim3(2, MTOT / 128), 256, GEMM_SMEM>>>(shi, slo, wuh, wul, out_b, out);
}

// round 11
// speedup vs baseline: 2.0678x; 1.2904x over previous
#include <cuda_runtime.h>
#include <cuda_bf16.h>
#include <math.h>
#include <stdint.h>

// Problem constants (fixed shapes)
#define BATCH   4
#define NQ      5440
#define NV      5440
#define EMBED   256
#define NHEADS  8
#define NLEV    4
#define NPTS    4
#define HDIM    32
#define MTOT    (BATCH * NQ)          // 21760 = 170 * 128

// ---------------------------------------------------------------------------
// Scratch (static device globals — no allocation anywhere)
// ---------------------------------------------------------------------------
__device__ float g_v[MTOT * EMBED];                    // projected value (f32)
__device__ float g_off[MTOT * EMBED];                  // sampling offsets
__device__ float g_aw[MTOT * 128];                     // attn logits

__device__ __nv_bfloat16 g_qhi[MTOT * EMBED],  g_qlo[MTOT * EMBED];   // query split
__device__ __nv_bfloat16 g_vhi[MTOT * EMBED],  g_vlo[MTOT * EMBED];   // value split
__device__ __nv_bfloat16 g_shi[MTOT * EMBED],  g_slo[MTOT * EMBED];   // sampled split

// transposed weight splits [N][K=256]
__device__ __nv_bfloat16 g_wvh[256 * 256], g_wvl[256 * 256];   // value_proj
__device__ __nv_bfloat16 g_wfh[256 * 256], g_wfl[256 * 256];   // offsets
__device__ __nv_bfloat16 g_wah[128 * 256], g_wal[128 * 256];   // attn
__device__ __nv_bfloat16 g_wuh[256 * 256], g_wul[256 * 256];   // out_proj

// ---------------------------------------------------------------------------
// Helpers
// ---------------------------------------------------------------------------
__device__ __forceinline__ uint32_t smem_u32(const void* p) {
    uint32_t a;
    asm("{ .reg .u64 t; cvta.to.shared.u64 t, %1; cvt.u32.u64 %0, t; }" : "=r"(a) : "l"(p));
    return a;
}

#define CP_ASYNC16(dst, src) \
    asm volatile("cp.async.cg.shared.global [%0], [%1], 16;" :: "r"(dst), "l"(src) : "memory")
#define CP_COMMIT() asm volatile("cp.async.commit_group;" ::: "memory")
#define CP_WAIT(n)  asm volatile("cp.async.wait_group %0;" :: "n"(n) : "memory")

__device__ __forceinline__ void ldm4(uint32_t* r, uint32_t addr) {
    asm volatile("ldmatrix.sync.aligned.m8n8.x4.shared.b16 {%0,%1,%2,%3}, [%4];"
                 : "=r"(r[0]), "=r"(r[1]), "=r"(r[2]), "=r"(r[3]) : "r"(addr));
}
__device__ __forceinline__ void mma16816(float* d, const uint32_t* a, const uint32_t* b) {
    asm volatile(
        "mma.sync.aligned.m16n8k16.row.col.f32.bf16.bf16.f32 "
        "{%0,%1,%2,%3}, {%4,%5,%6,%7}, {%8,%9}, {%0,%1,%2,%3};"
        : "+f"(d[0]), "+f"(d[1]), "+f"(d[2]), "+f"(d[3])
        : "r"(a[0]), "r"(a[1]), "r"(a[2]), "r"(a[3]), "r"(b[0]), "r"(b[1]));
}

// ---------------------------------------------------------------------------
// Fused activation decompose: value then query, f32 -> bf16 hi + lo residual
// ---------------------------------------------------------------------------
#define N4 (MTOT * EMBED / 4)
__global__ __launch_bounds__(256)
void decomp_act2(const float4* __restrict__ value, const float4* __restrict__ query,
                 uint2* __restrict__ vhi, uint2* __restrict__ vlo,
                 uint2* __restrict__ qhi, uint2* __restrict__ qlo) {
    int i = blockIdx.x * 256 + threadIdx.x;
    const float4* src; uint2 *hi, *lo;
    if (i < N4) { src = value; hi = vhi; lo = vlo; }
    else        { src = query; hi = qhi; lo = qlo; i -= N4; }
    float4 x = src[i];
    float v[4] = {x.x, x.y, x.z, x.w};
    union { __nv_bfloat16 b[4]; uint2 u; } H, L;
#pragma unroll
    for (int j = 0; j < 4; j++) {
        H.b[j] = __float2bfloat16(v[j]);
        L.b[j] = __float2bfloat16(v[j] - __bfloat162float(H.b[j]));
    }
    hi[i] = H.u;
    lo[i] = L.u;
}

// ---------------------------------------------------------------------------
// Fused weight decompose + transpose (all 4 weights in one launch).
// 32x32 smem tiles; coalesced reads AND writes. 224 tiles total.
// ---------------------------------------------------------------------------
__global__ __launch_bounds__(256)
void decomp_w_all(const float* __restrict__ Wv, const float* __restrict__ Wf,
                  const float* __restrict__ Wa, const float* __restrict__ Wu,
                  __nv_bfloat16* __restrict__ wvh, __nv_bfloat16* __restrict__ wvl,
                  __nv_bfloat16* __restrict__ wfh, __nv_bfloat16* __restrict__ wfl,
                  __nv_bfloat16* __restrict__ wah, __nv_bfloat16* __restrict__ wal,
                  __nv_bfloat16* __restrict__ wuh, __nv_bfloat16* __restrict__ wul) {
    __shared__ float tile[32][33];
    int id = blockIdx.x;
    const float* W; __nv_bfloat16 *hiT, *loT; int Nw, t;
    if (id < 64)       { W = Wv; hiT = wvh; loT = wvl; Nw = 256; t = id; }
    else if (id < 128) { W = Wf; hiT = wfh; loT = wfl; Nw = 256; t = id - 64; }
    else if (id < 160) { W = Wa; hiT = wah; loT = wal; Nw = 128; t = id - 128; }
    else               { W = Wu; hiT = wuh; loT = wul; Nw = 256; t = id - 160; }
    int ntiles_n = Nw >> 5;
    int tk = t / ntiles_n, tn = t % ntiles_n;
    int tx = threadIdx.x & 31, ty = threadIdx.x >> 5;   // 32 x 8

#pragma unroll
    for (int j = 0; j < 4; j++) {
        int k = tk * 32 + ty + j * 8;
        tile[ty + j * 8][tx] = W[(size_t)k * Nw + tn * 32 + tx];
    }
    __syncthreads();
#pragma unroll
    for (int j = 0; j < 4; j++) {
        int n = tn * 32 + ty + j * 8;
        float x = tile[tx][ty + j * 8];
        __nv_bfloat16 h = __float2bfloat16(x);
        size_t o = (size_t)n * 256 + tk * 32 + tx;
        hiT[o] = h;
        loT[o] = __float2bfloat16(x - __bfloat162float(h));
    }
}

// ---------------------------------------------------------------------------
// Tensor-core GEMM (legacy mma.sync path):
//   C[M,N] = A[M,256] @ W[256,N] + bias, bf16 3-product split, fp32 accum.
// Block 128x128, BK=32, 8 warps (4M x 2N), warp tile 32x64, 2-stage cp.async.
// ---------------------------------------------------------------------------
#define STAGE_BYTES 32768            // 4 tiles x 8KB (Ahi,Alo,Bhi,Blo)
#define GEMM_SMEM   (2 * STAGE_BYTES)

__device__ void mma_gemm_body(char* sm,
                              const __nv_bfloat16* __restrict__ Ahi,
                              const __nv_bfloat16* __restrict__ Alo,
                              const __nv_bfloat16* __restrict__ Bhi,
                              const __nv_bfloat16* __restrict__ Blo,
                              const float* __restrict__ bias,
                              float* __restrict__ C, int N, int bm, int bn)
{
    const int t = threadIdx.x, lane = t & 31, warp = t >> 5;
    const int wm = (warp >> 1) * 32;
    const int wn = (warp & 1) * 64;

    const uint32_t sbase = smem_u32(sm);

    const char* gsrc[4] = {
        (const char*)(Ahi + (size_t)bm * 256), (const char*)(Alo + (size_t)bm * 256),
        (const char*)(Bhi + (size_t)bn * 256), (const char*)(Blo + (size_t)bn * 256)
    };
    const int lrow = t >> 2, lseg = t & 3;

    float acc[2][8][4];
#pragma unroll
    for (int a = 0; a < 2; a++)
#pragma unroll
        for (int b = 0; b < 8; b++)
#pragma unroll
            for (int d = 0; d < 4; d++) acc[a][b][d] = 0.0f;

    const int arow_l = lane & 15;
    const int aseg_l = lane >> 4;
    const int brow_l = (lane & 7) + ((lane >> 4) << 3);
    const int bseg_l = (lane >> 3) & 1;

#define LOAD_CHUNK(c, s) do {                                                   \
        uint32_t st_ = sbase + (s) * STAGE_BYTES;                               \
        _Pragma("unroll")                                                       \
        for (int it_ = 0; it_ < 2; it_++) {                                     \
            int row_ = lrow + it_ * 64;                                         \
            uint32_t so_ = (uint32_t)(row_ * 64 + ((lseg ^ (row_ & 3)) << 4));  \
            size_t go_ = (size_t)row_ * 512 + (size_t)(c) * 64 + lseg * 16;     \
            CP_ASYNC16(st_ +      0 + so_, gsrc[0] + go_);                      \
            CP_ASYNC16(st_ +  8192 + so_, gsrc[1] + go_);                       \
            CP_ASYNC16(st_ + 16384 + so_, gsrc[2] + go_);                       \
            CP_ASYNC16(st_ + 24576 + so_, gsrc[3] + go_);                       \
        }                                                                       \
        CP_COMMIT();                                                            \
    } while (0)

    LOAD_CHUNK(0, 0);

    for (int c = 0; c < 8; c++) {
        if (c < 7) { LOAD_CHUNK(c + 1, (c + 1) & 1); CP_WAIT(1); }
        else       { CP_WAIT(0); }
        __syncthreads();

        const uint32_t st = sbase + (c & 1) * STAGE_BYTES;
#pragma unroll
        for (int kk = 0; kk < 2; kk++) {
            uint32_t ah[2][4], al[2][4];
#pragma unroll
            for (int mt = 0; mt < 2; mt++) {
                int row = wm + mt * 16 + arow_l;
                int seg = kk * 2 + aseg_l;
                uint32_t ad = st + (uint32_t)(row * 64 + ((seg ^ (row & 3)) << 4));
                ldm4(ah[mt], ad);
                ldm4(al[mt], ad + 8192);
            }
#pragma unroll
            for (int np = 0; np < 4; np++) {
                int row = wn + np * 16 + brow_l;
                int seg = kk * 2 + bseg_l;
                uint32_t bd = st + 16384 + (uint32_t)(row * 64 + ((seg ^ (row & 3)) << 4));
                uint32_t bh[4], bl[4];
                ldm4(bh, bd);
                ldm4(bl, bd + 8192);
#pragma unroll
                for (int half = 0; half < 2; half++) {
                    int nt = np * 2 + half;
#pragma unroll
                    for (int mt = 0; mt < 2; mt++) {
                        mma16816(acc[mt][nt], ah[mt], bh + half * 2);  // hi*hi
                        mma16816(acc[mt][nt], ah[mt], bl + half * 2);  // hi*lo
                        mma16816(acc[mt][nt], al[mt], bh + half * 2);  // lo*hi
                    }
                }
            }
        }
        __syncthreads();
    }
#undef LOAD_CHUNK

    const int r0 = bm + wm + (lane >> 2);
    const int c0 = bn + wn + (lane & 3) * 2;
#pragma unroll
    for (int nt = 0; nt < 8; nt++) {
        int col = c0 + nt * 8;
        float b0 = bias[col];
        float b1 = bias[col + 1];
#pragma unroll
        for (int mt = 0; mt < 2; mt++) {
            int row = r0 + mt * 16;
            float2 lo2, hi2;
            lo2.x = acc[mt][nt][0] + b0;
            lo2.y = acc[mt][nt][1] + b1;
            hi2.x = acc[mt][nt][2] + b0;
            hi2.y = acc[mt][nt][3] + b1;
            *(float2*)&C[(size_t)row * N + col]       = lo2;
            *(float2*)&C[(size_t)(row + 8) * N + col] = hi2;
        }
    }
}

// Fused launch: value-proj (2 N-tiles) + offsets (2) + attn (1) => grid.x = 5
__global__ __launch_bounds__(256, 1)
void mma_gemm_fused(const __nv_bfloat16* valhi, const __nv_bfloat16* vallo,
                    const __nv_bfloat16* qhi,   const __nv_bfloat16* qlo,
                    const __nv_bfloat16* wvh,   const __nv_bfloat16* wvl,
                    const __nv_bfloat16* wfh,   const __nv_bfloat16* wfl,
                    const __nv_bfloat16* wah,   const __nv_bfloat16* wal,
                    const float* vb, const float* fb, const float* ab,
                    float* Cv, float* Cf, float* Ca) {
    extern __shared__ char smem[];
    int bx = blockIdx.x, bm = blockIdx.y * 128;
    const __nv_bfloat16 *Ah, *Al, *Bh, *Bl;
    const float* bias; float* C; int N, bn;
    if (bx < 2)      { Ah = valhi; Al = vallo; Bh = wvh; Bl = wvl; bias = vb; C = Cv; N = 256; bn = bx * 128; }
    else if (bx < 4) { Ah = qhi;   Al = qlo;   Bh = wfh; Bl = wfl; bias = fb; C = Cf; N = 256; bn = (bx - 2) * 128; }
    else             { Ah = qhi;   Al = qlo;   Bh = wah; Bl = wal; bias = ab; C = Ca; N = 128; bn = 0; }
    mma_gemm_body(smem, Ah, Al, Bh, Bl, bias, C, N, bm, bn);
}

__global__ __launch_bounds__(256, 1)
void mma_gemm_out(const __nv_bfloat16* shi, const __nv_bfloat16* slo,
                  const __nv_bfloat16* wuh, const __nv_bfloat16* wul,
                  const float* ob, float* C) {
    extern __shared__ char smem[];
    mma_gemm_body(smem, shi, slo, wuh, wul, ob, C, 256, blockIdx.y * 128, blockIdx.x * 128);
}

// ---------------------------------------------------------------------------
// Deformable sampling + softmax, v2: float4 gather groups.
// One warp per (b,q,head). Lanes <16 do softmax + bilinear setup, stage
// (byte-offset, weight) pairs in smem. Gather: lane group g=lane>>3 handles
// corner c%4==g; each lane reads float4 (4 head dims) -> 16 LDG.128 total.
// Cross-group butterfly reduce; lanes 0-7 write hi split, 8-15 write lo.
// ---------------------------------------------------------------------------
__global__ __launch_bounds__(256)
void msda_sample(const float* __restrict__ vbuf, const float* __restrict__ offbuf,
                 const float* __restrict__ awbuf, const float* __restrict__ refp,
                 __nv_bfloat16* __restrict__ shi, __nv_bfloat16* __restrict__ slo)
{
    __shared__ uint2 pairs[8][64];            // [warp][point*4 + corner] = {byteoff, w}
    const unsigned FULL = 0xffffffffu;
    const int wwarp = threadIdx.x >> 5;
    const int lane  = threadIdx.x & 31;
    const int wg = blockIdx.x * 8 + wwarp;    // grid is exact: MTOT*NHEADS/8 blocks

    const int h  = wg & 7;
    const int bq = wg >> 3;
    const int b  = bq / NQ;

    // softmax over 16 (level,point) logits
    float logit = -1e30f;
    if (lane < 16) logit = awbuf[(size_t)bq * 128 + h * 16 + lane];
    float m = logit;
#pragma unroll
    for (int o = 16; o >= 1; o >>= 1) m = fmaxf(m, __shfl_xor_sync(FULL, m, o));
    float e = (lane < 16) ? __expf(logit - m) : 0.0f;
    float s = e;
#pragma unroll
    for (int o = 16; o >= 1; o >>= 1) s += __shfl_xor_sync(FULL, s, o);
    float wgt = e / s;

    if (lane < 16) {
        int l = lane >> 2;
        int W = 64 >> l, H = 64 >> l;
        int base = (16384 - (16384 >> (2 * l))) / 3;
        float Wf = (float)W, Hf = (float)H;

        const float* rp = refp + ((size_t)bq * NLEV + l) * 2;
        const float2 op = *(const float2*)(offbuf + (size_t)bq * EMBED + h * 32 + 2 * lane);

        float px = (rp[0] + op.x * (1.0f / Wf)) * Wf - 0.5f;
        float py = (rp[1] + op.y * (1.0f / Hf)) * Hf - 0.5f;
        float x0f = floorf(px), y0f = floorf(py);
        float wx = px - x0f, wy = py - y0f;
        int x0 = (int)x0f, y0 = (int)y0f;

        uint4 pk[2];
        uint32_t* pu = (uint32_t*)pk;
#pragma unroll
        for (int c = 0; c < 4; c++) {
            int dx = c & 1, dy = c >> 1;
            int xi = x0 + dx, yi = y0 + dy;
            bool valid = (xi >= 0) & (xi < W) & (yi >= 0) & (yi < H);
            int xc = min(max(xi, 0), W - 1);
            int yc = min(max(yi, 0), H - 1);
            float wc = (dx ? wx : 1.0f - wx) * (dy ? wy : 1.0f - wy);
            pu[c * 2 + 0] = (uint32_t)((base + yc * W + xc) << 10);   // byte offset (row=1024B)
            pu[c * 2 + 1] = __float_as_uint(valid ? wgt * wc : 0.0f);
        }
        *(uint4*)&pairs[wwarp][lane * 4]     = pk[0];
        *(uint4*)&pairs[wwarp][lane * 4 + 2] = pk[1];
    }
    __syncwarp(FULL);

    // gather: group g handles corners with c==g; lane reads 4 dims (float4)
    const int g  = lane >> 3;
    const int li = lane & 7;
    const char* vb = (const char*)vbuf + (size_t)b * NV * 1024 + h * 128 + li * 16;
    float4 acc = make_float4(0.0f, 0.0f, 0.0f, 0.0f);
#pragma unroll
    for (int i = 0; i < 16; i++) {
        uint2 p = pairs[wwarp][i * 4 + g];
        float w = __uint_as_float(p.y);
        float4 v4 = *(const float4*)(vb + p.x);
        acc.x = fmaf(w, v4.x, acc.x);
        acc.y = fmaf(w, v4.y, acc.y);
        acc.z = fmaf(w, v4.z, acc.z);
        acc.w = fmaf(w, v4.w, acc.w);
    }
    // reduce across the 4 groups (xor 8, 16)
#pragma unroll
    for (int o = 8; o <= 16; o <<= 1) {
        acc.x += __shfl_xor_sync(FULL, acc.x, o);
        acc.y += __shfl_xor_sync(FULL, acc.y, o);
        acc.z += __shfl_xor_sync(FULL, acc.z, o);
        acc.w += __shfl_xor_sync(FULL, acc.w, o);
    }

    if (lane < 16) {
        size_t o = (size_t)bq * EMBED + h * HDIM + li * 4;
        float v[4] = {acc.x, acc.y, acc.z, acc.w};
        union { __nv_bfloat16 b[4]; uint2 u; } P;
        if (lane < 8) {
#pragma unroll
            for (int j = 0; j < 4; j++) P.b[j] = __float2bfloat16(v[j]);
            *(uint2*)(shi + o) = P.u;
        } else {
#pragma unroll
            for (int j = 0; j < 4; j++) {
                __nv_bfloat16 hh = __float2bfloat16(v[j]);
                P.b[j] = __float2bfloat16(v[j] - __bfloat162float(hh));
            }
            *(uint2*)(slo + o) = P.u;
        }
    }
}

// ---------------------------------------------------------------------------
// kernel_launch
// ---------------------------------------------------------------------------
extern "C" void kernel_launch(void* const* d_in, const int* in_sizes, int n_in,
                              void* d_out, int out_size)
{
    const float* query   = (const float*)d_in[0];
    const float* value   = (const float*)d_in[1];
    const float* refp    = (const float*)d_in[2];
    const float* vproj_w = (const float*)d_in[3];
    const float* vproj_b = (const float*)d_in[4];
    const float* off_w   = (const float*)d_in[5];
    const float* off_b   = (const float*)d_in[6];
    const float* aw_w    = (const float*)d_in[7];
    const float* aw_b    = (const float*)d_in[8];
    const float* out_w   = (const float*)d_in[9];
    const float* out_b   = (const float*)d_in[10];
    float* out = (float*)d_out;

    float *v, *off, *aw;
    __nv_bfloat16 *qhi, *qlo, *vhi, *vlo, *shi, *slo;
    __nv_bfloat16 *wvh, *wvl, *wfh, *wfl, *wah, *wal, *wuh, *wul;
    cudaGetSymbolAddress((void**)&v,   g_v);
    cudaGetSymbolAddress((void**)&off, g_off);
    cudaGetSymbolAddress((void**)&aw,  g_aw);
    cudaGetSymbolAddress((void**)&qhi, g_qhi); cudaGetSymbolAddress((void**)&qlo, g_qlo);
    cudaGetSymbolAddress((void**)&vhi, g_vhi); cudaGetSymbolAddress((void**)&vlo, g_vlo);
    cudaGetSymbolAddress((void**)&shi, g_shi); cudaGetSymbolAddress((void**)&slo, g_slo);
    cudaGetSymbolAddress((void**)&wvh, g_wvh); cudaGetSymbolAddress((void**)&wvl, g_wvl);
    cudaGetSymbolAddress((void**)&wfh, g_wfh); cudaGetSymbolAddress((void**)&wfl, g_wfl);
    cudaGetSymbolAddress((void**)&wah, g_wah); cudaGetSymbolAddress((void**)&wal, g_wal);
    cudaGetSymbolAddress((void**)&wuh, g_wuh); cudaGetSymbolAddress((void**)&wul, g_wul);

    cudaFuncSetAttribute(mma_gemm_fused, cudaFuncAttributeMaxDynamicSharedMemorySize, GEMM_SMEM);
    cudaFuncSetAttribute(mma_gemm_out,   cudaFuncAttributeMaxDynamicSharedMemorySize, GEMM_SMEM);

    // fused decomposes: activations (value+query) and all 4 weights
    decomp_act2<<<(2 * N4) / 256, 256>>>((const float4*)value, (const float4*)query,
                                         (uint2*)vhi, (uint2*)vlo, (uint2*)qhi, (uint2*)qlo);
    decomp_w_all<<<224, 256>>>(vproj_w, off_w, aw_w, out_w,
                               wvh, wvl, wfh, wfl, wah, wal, wuh, wul);

    // fused value/offsets/attn projections: 5 N-tiles x 170 M-tiles
    mma_gemm_fused<<<dim3(5, MTOT / 128), 256, GEMM_SMEM>>>(
        vhi, vlo, qhi, qlo, wvh, wvl, wfh, wfl, wah, wal,
        vproj_b, off_b, aw_b, v, off, aw);

    // softmax + deformable bilinear sampling (emits bf16 split directly)
    msda_sample<<<(MTOT * NHEADS) / 8, 256>>>(v, off, aw, refp, shi, slo);

    // output projection straight into d_out
    mma_gemm_out<<<dim3(2, MTOT / 128), 256, GEMM_SMEM>>>(shi, slo, wuh, wul, out_b, out);
}